// round 1
// baseline (speedup 1.0000x reference)
#include <cuda_runtime.h>
#include <math.h>

#define SEQ   1024
#define EMB   2880
#define NH    64
#define NKV   8
#define HDIM  64
#define HD    (NH*HDIM)    // 4096
#define KVD   (NKV*HDIM)   // 512
#define WIN   128
#define QT    8
#define NKEY  (QT + WIN - 1)   // 135
#define KSTR  65

// Scratch (device globals: no allocation allowed in kernel_launch)
__device__ float g_q[SEQ*HD];
__device__ float g_k[SEQ*KVD];
__device__ float g_v[SEQ*KVD];
__device__ float g_att[SEQ*HD];

// ---------------------------------------------------------------------------
// GEMM: C[M,N] = A[M,K] @ B[N,K]^T + bias[N]
// BM=128, BN=64, BK=16, TM=8, TN=4, 256 threads. All dims divide exactly.
// ---------------------------------------------------------------------------
__global__ void gemm_bias_kernel(const float* __restrict__ A,
                                 const float* __restrict__ Bw,
                                 const float* __restrict__ bias,
                                 float* __restrict__ C,
                                 int M, int N, int K) {
    const int BM = 128, BN = 64, BK = 16, TM = 8, TN = 4;
    __shared__ __align__(16) float As[BK][BM + 4];   // [k][m]
    __shared__ __align__(16) float Bs[BK][BN + 4];   // [k][n]

    int tid = threadIdx.x;
    int bm = blockIdx.y * BM;
    int bn = blockIdx.x * BN;
    int ty = tid / (BN / TN);   // 0..15
    int tx = tid % (BN / TN);   // 0..15

    float acc[TM][TN];
#pragma unroll
    for (int i = 0; i < TM; i++)
#pragma unroll
        for (int j = 0; j < TN; j++) acc[i][j] = 0.0f;

    for (int kt = 0; kt < K; kt += BK) {
        // A tile: 128x16 = 512 float4, 2 per thread (transposed store)
#pragma unroll
        for (int l = 0; l < 2; l++) {
            int idx = tid + l * 256;          // 0..511
            int r   = idx >> 2;               // 0..127
            int cq  = (idx & 3) * 4;          // 0,4,8,12
            float4 va = *(const float4*)(A + (size_t)(bm + r) * K + kt + cq);
            As[cq + 0][r] = va.x;
            As[cq + 1][r] = va.y;
            As[cq + 2][r] = va.z;
            As[cq + 3][r] = va.w;
        }
        // B tile: 64x16 = 256 float4, 1 per thread
        {
            int r  = tid >> 2;                // 0..63
            int cq = (tid & 3) * 4;
            float4 vb = *(const float4*)(Bw + (size_t)(bn + r) * K + kt + cq);
            Bs[cq + 0][r] = vb.x;
            Bs[cq + 1][r] = vb.y;
            Bs[cq + 2][r] = vb.z;
            Bs[cq + 3][r] = vb.w;
        }
        __syncthreads();

#pragma unroll
        for (int k = 0; k < BK; k++) {
            float4 a0 = *(const float4*)&As[k][ty * TM];
            float4 a1 = *(const float4*)&As[k][ty * TM + 4];
            float4 b0 = *(const float4*)&Bs[k][tx * TN];
            float a[TM] = {a0.x, a0.y, a0.z, a0.w, a1.x, a1.y, a1.z, a1.w};
            float b[TN] = {b0.x, b0.y, b0.z, b0.w};
#pragma unroll
            for (int i = 0; i < TM; i++)
#pragma unroll
                for (int j = 0; j < TN; j++)
                    acc[i][j] += a[i] * b[j];
        }
        __syncthreads();
    }

#pragma unroll
    for (int i = 0; i < TM; i++) {
        int row = bm + ty * TM + i;
#pragma unroll
        for (int j = 0; j < TN; j++) {
            int col = bn + tx * TN + j;
            C[(size_t)row * N + col] = acc[i][j] + bias[col];
        }
    }
}

// ---------------------------------------------------------------------------
// RoPE (YaRN): in-place on g_q [SEQ,NH,HDIM] and g_k [SEQ,NKV,HDIM]
// ---------------------------------------------------------------------------
__global__ void rope_kernel(const int* __restrict__ positions) {
    int s   = blockIdx.x;
    int tid = threadIdx.x;
    __shared__ float csh[32], ssh[32];

    if (tid < 32) {
        float i2 = 2.0f * (float)tid;
        float pf = powf(150000.0f, i2 / 64.0f);
        double lbase = 2.0 * log(150000.0);
        double low  = 64.0 * log(4096.0 / (32.0 * 2.0 * M_PI)) / lbase;
        double high = 64.0 * log(4096.0 / (1.0  * 2.0 * M_PI)) / lbase;
        if (low  < 0.0)  low  = 0.0;
        if (high > 31.0) high = 31.0;
        float ramp = ((float)tid - (float)low) / (float)(high - low);
        ramp = fminf(fmaxf(ramp, 0.0f), 1.0f);
        float invf = (1.0f / (32.0f * pf)) * ramp + (1.0f / pf) * (1.0f - ramp);
        float mscale = 0.1f * logf(32.0f) + 1.0f;
        float ang = (float)positions[s] * invf;
        csh[tid] = cosf(ang) * mscale;
        ssh[tid] = sinf(ang) * mscale;
    }
    __syncthreads();

    for (int item = tid; item < (NH + NKV) * 32; item += blockDim.x) {
        int h = item >> 5;
        int i = item & 31;
        float* base = (h < NH) ? (g_q + (size_t)s * HD + h * HDIM)
                               : (g_k + (size_t)s * KVD + (h - NH) * HDIM);
        float x0 = base[i];
        float x1 = base[i + 32];
        base[i]      = x0 * csh[i] - x1 * ssh[i];
        base[i + 32] = x1 * csh[i] + x0 * ssh[i];
    }
}

// ---------------------------------------------------------------------------
// Sliding-window attention with sink softmax.
// One block per (kv_head, 8-query tile). 256 threads = 8 warps, warp w = head
// kv*8+w. K/V window staged in SMEM (stride 65: conflict-free).
// ---------------------------------------------------------------------------
__global__ void attn_kernel(const float* __restrict__ sinks) {
    extern __shared__ float smem[];
    float* k_sh = smem;                       // NKEY*KSTR
    float* v_sh = k_sh + NKEY * KSTR;         // NKEY*KSTR
    float* q_sh = v_sh + NKEY * KSTR;         // 8*QT*64
    float* p_sh = q_sh + 8 * QT * 64;         // 8*WIN

    int kvh  = blockIdx.x;        // 0..7
    int q0   = blockIdx.y * QT;
    int base = q0 - (WIN - 1);
    int tid  = threadIdx.x;
    int w    = tid >> 5;
    int lane = tid & 31;

    // Stage K/V window
    for (int idx = tid; idx < NKEY * HDIM; idx += 256) {
        int off = idx >> 6;
        int d   = idx & 63;
        int sg  = base + off;
        float kvval = 0.0f, vvval = 0.0f;
        if (sg >= 0) {
            kvval = g_k[(size_t)sg * KVD + kvh * HDIM + d];
            vvval = g_v[(size_t)sg * KVD + kvh * HDIM + d];
        }
        k_sh[off * KSTR + d] = kvval;
        v_sh[off * KSTR + d] = vvval;
    }
    // Stage Q (8 heads x QT queries x 64)
    for (int idx = tid; idx < 8 * QT * 64; idx += 256) {
        int wq = idx >> 9;
        int j  = (idx >> 6) & 7;
        int d  = idx & 63;
        q_sh[idx] = g_q[(size_t)(q0 + j) * HD + (kvh * 8 + wq) * HDIM + d];
    }
    __syncthreads();

    int h = kvh * 8 + w;
    float sinkv = sinks[h];
    const float* qbase = q_sh + w * QT * 64;

    for (int j = 0; j < QT; j++) {
        const float* qv = qbase + j * 64;
        float sc[4];
        bool  val[4];
        float mx = -INFINITY;
#pragma unroll
        for (int m = 0; m < 4; m++) {
            int t   = lane + 32 * m;      // 0..127 within window
            int off = j + t;
            int sg  = base + off;
            val[m] = (sg >= 0);
            float acc = 0.0f;
            const float* kr = k_sh + off * KSTR;
#pragma unroll 16
            for (int d = 0; d < 64; d++) acc += qv[d] * kr[d];
            sc[m] = acc * 0.125f;
            if (val[m]) mx = fmaxf(mx, sc[m]);
        }
#pragma unroll
        for (int o = 16; o; o >>= 1) mx = fmaxf(mx, __shfl_xor_sync(0xFFFFFFFFu, mx, o));
        mx = fmaxf(mx, sinkv);

        float lsum = 0.0f;
        float p[4];
#pragma unroll
        for (int m = 0; m < 4; m++) {
            p[m] = val[m] ? __expf(sc[m] - mx) : 0.0f;
            lsum += p[m];
        }
#pragma unroll
        for (int o = 16; o; o >>= 1) lsum += __shfl_xor_sync(0xFFFFFFFFu, lsum, o);
        float inv = 1.0f / (lsum + __expf(sinkv - mx));

#pragma unroll
        for (int m = 0; m < 4; m++)
            p_sh[w * WIN + lane + 32 * m] = p[m] * inv;
        __syncwarp();

        float o0 = 0.0f, o1 = 0.0f;
        const float* vb = v_sh + j * KSTR;
        const float* pw = p_sh + w * WIN;
#pragma unroll 8
        for (int t = 0; t < WIN; t++) {
            float pp = pw[t];
            o0 += pp * vb[t * KSTR + lane];
            o1 += pp * vb[t * KSTR + lane + 32];
        }
        size_t ob = (size_t)(q0 + j) * HD + (size_t)h * HDIM;
        g_att[ob + lane]      = o0;
        g_att[ob + lane + 32] = o1;
        __syncwarp();
    }
}

// ---------------------------------------------------------------------------
extern "C" void kernel_launch(void* const* d_in, const int* in_sizes, int n_in,
                              void* d_out, int out_size) {
    (void)in_sizes; (void)n_in; (void)out_size;
    const float* x     = (const float*)d_in[0];
    const int*   pos   = (const int*)  d_in[1];
    const float* Wq    = (const float*)d_in[2];
    const float* bq    = (const float*)d_in[3];
    const float* Wk    = (const float*)d_in[4];
    const float* bk    = (const float*)d_in[5];
    const float* Wv    = (const float*)d_in[6];
    const float* bv    = (const float*)d_in[7];
    const float* Wo    = (const float*)d_in[8];
    const float* bo    = (const float*)d_in[9];
    const float* sinks = (const float*)d_in[10];
    float* out = (float*)d_out;

    float *qp, *kp, *vp, *ap;
    cudaGetSymbolAddress((void**)&qp, g_q);
    cudaGetSymbolAddress((void**)&kp, g_k);
    cudaGetSymbolAddress((void**)&vp, g_v);
    cudaGetSymbolAddress((void**)&ap, g_att);

    // QKV projections
    gemm_bias_kernel<<<dim3(HD / 64, SEQ / 128), 256>>>(x, Wq, bq, qp, SEQ, HD,  EMB);
    gemm_bias_kernel<<<dim3(KVD / 64, SEQ / 128), 256>>>(x, Wk, bk, kp, SEQ, KVD, EMB);
    gemm_bias_kernel<<<dim3(KVD / 64, SEQ / 128), 256>>>(x, Wv, bv, vp, SEQ, KVD, EMB);

    // RoPE
    rope_kernel<<<SEQ, 256>>>(pos);

    // Attention
    size_t attn_smem = (size_t)(2 * NKEY * KSTR + 8 * QT * 64 + 8 * WIN) * sizeof(float);
    cudaFuncSetAttribute(attn_kernel, cudaFuncAttributeMaxDynamicSharedMemorySize,
                         (int)attn_smem);
    attn_kernel<<<dim3(NKV, SEQ / QT), 256, attn_smem>>>(sinks);

    // Output projection
    gemm_bias_kernel<<<dim3(EMB / 64, SEQ / 128), 256>>>(ap, Wo, bo, out, SEQ, EMB, HD);
}

// round 3
// speedup vs baseline: 2.3948x; 2.3948x over previous
#include <cuda_runtime.h>
#include <cuda_bf16.h>
#include <math.h>
#include <stdint.h>

#define SEQ   1024
#define EMB   2880
#define NH    64
#define NKV   8
#define HDIM  64
#define HD    4096
#define KVD   512
#define WIN   128
#define QT    8
#define NKEY  135
#define KSTR  68

// Scratch (device globals: no allocation allowed)
__device__ float g_q[SEQ*HD];
__device__ float g_k[SEQ*KVD];
__device__ float g_v[SEQ*KVD];
__device__ float g_att[SEQ*HD];

// ============================ helpers ============================
__device__ __forceinline__ uint32_t smem_u32(const void* p) {
    uint32_t a;
    asm("{ .reg .u64 t; cvta.to.shared.u64 t, %1; cvt.u32.u64 %0, t; }"
        : "=r"(a) : "l"(p));
    return a;
}

#define LDSM4(d, addr) \
    asm volatile("ldmatrix.sync.aligned.m8n8.x4.shared.b16 {%0,%1,%2,%3}, [%4];" \
        : "=r"((d)[0]), "=r"((d)[1]), "=r"((d)[2]), "=r"((d)[3]) : "r"(addr))

#define MMA16816(d, a, b0, b1) \
    asm volatile("mma.sync.aligned.m16n8k16.row.col.f32.bf16.bf16.f32 " \
        "{%0,%1,%2,%3}, {%4,%5,%6,%7}, {%8,%9}, {%0,%1,%2,%3};" \
        : "+f"((d)[0]), "+f"((d)[1]), "+f"((d)[2]), "+f"((d)[3]) \
        : "r"((a)[0]), "r"((a)[1]), "r"((a)[2]), "r"((a)[3]), "r"(b0), "r"(b1))

// split one float4 into bf16 hi + bf16 lo pairs and store 8B each to smem
__device__ __forceinline__ void split_store(float4 v, uint32_t hiaddr, uint32_t loaddr) {
    __nv_bfloat162 h01 = __floats2bfloat162_rn(v.x, v.y);   // .x lo half
    __nv_bfloat162 h23 = __floats2bfloat162_rn(v.z, v.w);
    float hx = __bfloat162float(h01.x), hy = __bfloat162float(h01.y);
    float hz = __bfloat162float(h23.x), hw = __bfloat162float(h23.y);
    __nv_bfloat162 l01 = __floats2bfloat162_rn(v.x - hx, v.y - hy);
    __nv_bfloat162 l23 = __floats2bfloat162_rn(v.z - hz, v.w - hw);
    uint32_t H0 = *(uint32_t*)&h01, H1 = *(uint32_t*)&h23;
    uint32_t L0 = *(uint32_t*)&l01, L1 = *(uint32_t*)&l23;
    asm volatile("st.shared.v2.b32 [%0], {%1, %2};" :: "r"(hiaddr), "r"(H0), "r"(H1) : "memory");
    asm volatile("st.shared.v2.b32 [%0], {%1, %2};" :: "r"(loaddr), "r"(L0), "r"(L1) : "memory");
}

// ============================ split-bf16 HMMA GEMM ============================
// C[128 x nvalid] = A[128,K] @ Bw[nvalid,K]^T + bias  (fp32 in/out)
// BM=128, BN=128, BK=32, 8 warps (2x4), warp tile 64x32, m16n8k16 bf16 x3 split.
#define GBM 128
#define GBN 128
#define GKC 32
#define ASTR 40                          // bf16 per smem row (32 + 8 pad)
#define REG_BYTES (128*ASTR*2)           // 10240 per region
#define BUF_BYTES (4*REG_BYTES)          // AH AL BH BL = 40960
#define GSMEM (2*BUF_BYTES + 512)        // 82432

__device__ __forceinline__ void gemm_tile(
        const float* __restrict__ A, int lda,
        const float* __restrict__ Bw, int ldb,
        const float* __restrict__ bias,
        float* __restrict__ C, int ldc,
        int K, int nvalid) {
    extern __shared__ char smem[];
    uint32_t sb = smem_u32(smem);
    float* bias_sh = (float*)(smem + 2 * BUF_BYTES);

    int tid  = threadIdx.x;
    int lane = tid & 31;
    int w    = tid >> 5;
    int bm   = blockIdx.y * GBM;
    int wm   = (w >> 2) * 64;
    int wn   = (w & 3) * 32;

    if (tid < GBN) bias_sh[tid] = (tid < nvalid) ? bias[tid] : 0.0f;

    // ldmatrix per-lane offsets (bytes)
    int r = lane & 7, g = lane >> 3;
    uint32_t aoff = (uint32_t)(((wm + ((g & 1) << 3) + r) * ASTR + ((g >> 1) << 3)) * 2);
    uint32_t boff = (uint32_t)(((wn + (((g >> 1) & 1) << 3) + r) * ASTR + ((g & 1) << 3)) * 2);

    float acc[4][4][4];
#pragma unroll
    for (int i = 0; i < 4; i++)
#pragma unroll
        for (int j = 0; j < 4; j++)
#pragma unroll
            for (int q = 0; q < 4; q++) acc[i][j][q] = 0.0f;

    float4 stA[4], stB[4];
    // prologue: tile 0 -> buffer 0
#pragma unroll
    for (int i = 0; i < 4; i++) {
        int idx = tid + i * 256;
        int row = idx >> 3, c4 = idx & 7;
        stA[i] = *(const float4*)(A + (size_t)(bm + row) * lda + c4 * 4);
        stB[i] = (row < nvalid) ? *(const float4*)(Bw + (size_t)row * ldb + c4 * 4)
                                : make_float4(0.f, 0.f, 0.f, 0.f);
    }
#pragma unroll
    for (int i = 0; i < 4; i++) {
        int idx = tid + i * 256;
        int row = idx >> 3, c4 = idx & 7;
        uint32_t o = (uint32_t)((row * ASTR + c4 * 4) * 2);
        split_store(stA[i], sb + o, sb + REG_BYTES + o);
        split_store(stB[i], sb + 2 * REG_BYTES + o, sb + 3 * REG_BYTES + o);
    }
    __syncthreads();

    int NC = K / GKC;
    for (int c = 0; c < NC; c++) {
        uint32_t buf = sb + (uint32_t)((c & 1) * BUF_BYTES);
        if (c + 1 < NC) {
            int kt = (c + 1) * GKC;
#pragma unroll
            for (int i = 0; i < 4; i++) {
                int idx = tid + i * 256;
                int row = idx >> 3, c4 = idx & 7;
                stA[i] = *(const float4*)(A + (size_t)(bm + row) * lda + kt + c4 * 4);
                stB[i] = (row < nvalid)
                       ? *(const float4*)(Bw + (size_t)row * ldb + kt + c4 * 4)
                       : make_float4(0.f, 0.f, 0.f, 0.f);
            }
        }
        // compute: 2 x k16 steps
#pragma unroll
        for (int ks = 0; ks < 2; ks++) {
            uint32_t kb = (uint32_t)(ks * 32);   // 16 bf16 = 32 bytes
            uint32_t aH[4][4], aL[4][4], bH[2][4], bL[2][4];
#pragma unroll
            for (int mf = 0; mf < 4; mf++) {
                uint32_t ad = buf + aoff + kb + (uint32_t)(mf * 16 * ASTR * 2);
                LDSM4(aH[mf], ad);
                LDSM4(aL[mf], ad + REG_BYTES);
            }
#pragma unroll
            for (int nf2 = 0; nf2 < 2; nf2++) {
                uint32_t bd = buf + 2 * REG_BYTES + boff + kb
                            + (uint32_t)(nf2 * 16 * ASTR * 2);
                LDSM4(bH[nf2], bd);
                LDSM4(bL[nf2], bd + REG_BYTES);
            }
#pragma unroll
            for (int mf = 0; mf < 4; mf++)
#pragma unroll
                for (int nf = 0; nf < 4; nf++) {
                    uint32_t b0h = bH[nf >> 1][(nf & 1) * 2];
                    uint32_t b1h = bH[nf >> 1][(nf & 1) * 2 + 1];
                    uint32_t b0l = bL[nf >> 1][(nf & 1) * 2];
                    uint32_t b1l = bL[nf >> 1][(nf & 1) * 2 + 1];
                    MMA16816(acc[mf][nf], aH[mf], b0h, b1h);
                    MMA16816(acc[mf][nf], aL[mf], b0h, b1h);
                    MMA16816(acc[mf][nf], aH[mf], b0l, b1l);
                }
        }
        if (c + 1 < NC) {
            uint32_t nbuf = sb + (uint32_t)(((c + 1) & 1) * BUF_BYTES);
#pragma unroll
            for (int i = 0; i < 4; i++) {
                int idx = tid + i * 256;
                int row = idx >> 3, c4 = idx & 7;
                uint32_t o = (uint32_t)((row * ASTR + c4 * 4) * 2);
                split_store(stA[i], nbuf + o, nbuf + REG_BYTES + o);
                split_store(stB[i], nbuf + 2 * REG_BYTES + o, nbuf + 3 * REG_BYTES + o);
            }
        }
        __syncthreads();
    }

    // epilogue: acc fragment -> C (+bias)
    int rr = lane >> 2, cc = (lane & 3) * 2;
#pragma unroll
    for (int mf = 0; mf < 4; mf++) {
        int row0 = bm + wm + mf * 16 + rr;
#pragma unroll
        for (int nf = 0; nf < 4; nf++) {
            int col = wn + nf * 8 + cc;
            if (col < nvalid) {
                float b0 = bias_sh[col], b1 = bias_sh[col + 1];
                float2 v0 = make_float2(acc[mf][nf][0] + b0, acc[mf][nf][1] + b1);
                float2 v1 = make_float2(acc[mf][nf][2] + b0, acc[mf][nf][3] + b1);
                *(float2*)(C + (size_t)row0 * ldc + col)       = v0;
                *(float2*)(C + (size_t)(row0 + 8) * ldc + col) = v1;
            }
        }
    }
}

// Fused QKV projection: n-tiles 0-31 -> Wq, 32-35 -> Wk, 36-39 -> Wv
__global__ void __launch_bounds__(256, 1)
qkv_gemm(const float* __restrict__ x,
         const float* __restrict__ Wq, const float* __restrict__ bq,
         const float* __restrict__ Wk, const float* __restrict__ bk,
         const float* __restrict__ Wv, const float* __restrict__ bv) {
    int nt = blockIdx.x;
    const float *B, *bi; float* C; int ldc;
    if (nt < 32)      { B = Wq + (size_t)nt * 128 * EMB; bi = bq + nt * 128; C = g_q + nt * 128; ldc = HD;  }
    else if (nt < 36) { int t = nt - 32; B = Wk + (size_t)t * 128 * EMB; bi = bk + t * 128; C = g_k + t * 128; ldc = KVD; }
    else              { int t = nt - 36; B = Wv + (size_t)t * 128 * EMB; bi = bv + t * 128; C = g_v + t * 128; ldc = KVD; }
    gemm_tile(x, EMB, B, EMB, bi, C, ldc, EMB, 128);
}

__global__ void __launch_bounds__(256, 1)
oproj_gemm(const float* __restrict__ Wo, const float* __restrict__ bo,
           float* __restrict__ out) {
    int n0 = blockIdx.x * 128;
    int nv = EMB - n0; if (nv > 128) nv = 128;
    gemm_tile(g_att, HD, Wo + (size_t)n0 * HD, HD, bo + n0, out + n0, EMB, HD, nv);
}

// ============================ RoPE (YaRN) ============================
__global__ void rope_kernel(const int* __restrict__ positions) {
    int s = blockIdx.x;
    int tid = threadIdx.x;
    __shared__ float csh[32], ssh[32];

    if (tid < 32) {
        float i2 = 2.0f * (float)tid;
        float pf = powf(150000.0f, i2 / 64.0f);
        double lbase = 2.0 * log(150000.0);
        double low  = 64.0 * log(4096.0 / (32.0 * 2.0 * M_PI)) / lbase;
        double high = 64.0 * log(4096.0 / (1.0  * 2.0 * M_PI)) / lbase;
        if (low  < 0.0)  low  = 0.0;
        if (high > 31.0) high = 31.0;
        float ramp = ((float)tid - (float)low) / (float)(high - low);
        ramp = fminf(fmaxf(ramp, 0.0f), 1.0f);
        float invf = (1.0f / (32.0f * pf)) * ramp + (1.0f / pf) * (1.0f - ramp);
        float mscale = 0.1f * logf(32.0f) + 1.0f;
        float ang = (float)positions[s] * invf;
        csh[tid] = cosf(ang) * mscale;
        ssh[tid] = sinf(ang) * mscale;
    }
    __syncthreads();

    for (int item = tid; item < (NH + NKV) * 32; item += blockDim.x) {
        int h = item >> 5;
        int i = item & 31;
        float* base = (h < NH) ? (g_q + (size_t)s * HD + h * HDIM)
                               : (g_k + (size_t)s * KVD + (h - NH) * HDIM);
        float x0 = base[i];
        float x1 = base[i + 32];
        base[i]      = x0 * csh[i] - x1 * ssh[i];
        base[i + 32] = x1 * csh[i] + x0 * ssh[i];
    }
}

// ============================ Attention ============================
// Block = (kv_head, 8-query tile). 8 warps, warp w = head kvh*8+w.
// q in registers; K/V smem stride 68 floats -> conflict-free.
__global__ void attn_kernel(const float* __restrict__ sinks) {
    extern __shared__ float asmem[];
    float* k_sh = asmem;                       // NKEY*KSTR
    float* v_sh = k_sh + NKEY * KSTR;          // NKEY*KSTR
    float* q_sh = v_sh + NKEY * KSTR;          // QT*512
    float* p_sh = q_sh + QT * 512;             // 8*WIN

    int kvh  = blockIdx.x;
    int q0   = blockIdx.y * QT;
    int base = q0 - (WIN - 1);
    int tid  = threadIdx.x;
    int w    = tid >> 5;
    int lane = tid & 31;

    for (int i4 = tid; i4 < NKEY * 16; i4 += 256) {
        int row = i4 >> 4, d4 = i4 & 15;
        int sg = base + row;
        float4 kv = make_float4(0.f, 0.f, 0.f, 0.f);
        float4 vv = make_float4(0.f, 0.f, 0.f, 0.f);
        if (sg >= 0) {
            kv = *(const float4*)(g_k + (size_t)sg * KVD + kvh * HDIM + d4 * 4);
            vv = *(const float4*)(g_v + (size_t)sg * KVD + kvh * HDIM + d4 * 4);
        }
        *(float4*)(k_sh + row * KSTR + d4 * 4) = kv;
        *(float4*)(v_sh + row * KSTR + d4 * 4) = vv;
    }
    for (int i4 = tid; i4 < QT * 128; i4 += 256) {
        int j = i4 >> 7, d4 = i4 & 127;
        *(float4*)(q_sh + j * 512 + d4 * 4) =
            *(const float4*)(g_q + (size_t)(q0 + j) * HD + kvh * 512 + d4 * 4);
    }
    __syncthreads();

    int h = kvh * 8 + w;
    float sinkv = sinks[h];

    for (int j = 0; j < QT; j++) {
        float4 qr[16];
        const float4* q4 = (const float4*)(q_sh + j * 512 + w * 64);
#pragma unroll
        for (int d = 0; d < 16; d++) qr[d] = q4[d];

        float sc[4];
        bool  val[4];
        float mx = -INFINITY;
#pragma unroll
        for (int m = 0; m < 4; m++) {
            int off = j + lane + 32 * m;
            int sg  = base + off;
            val[m] = (sg >= 0);
            const float4* k4 = (const float4*)(k_sh + off * KSTR);
            float acc = 0.0f;
#pragma unroll
            for (int d = 0; d < 16; d++) {
                float4 kv = k4[d];
                acc += qr[d].x * kv.x + qr[d].y * kv.y
                     + qr[d].z * kv.z + qr[d].w * kv.w;
            }
            sc[m] = acc * 0.125f;
            if (val[m]) mx = fmaxf(mx, sc[m]);
        }
#pragma unroll
        for (int o = 16; o; o >>= 1) mx = fmaxf(mx, __shfl_xor_sync(0xFFFFFFFFu, mx, o));
        mx = fmaxf(mx, sinkv);

        float lsum = 0.0f;
        float p[4];
#pragma unroll
        for (int m = 0; m < 4; m++) {
            p[m] = val[m] ? __expf(sc[m] - mx) : 0.0f;
            lsum += p[m];
        }
#pragma unroll
        for (int o = 16; o; o >>= 1) lsum += __shfl_xor_sync(0xFFFFFFFFu, lsum, o);
        float inv = 1.0f / (lsum + __expf(sinkv - mx));

#pragma unroll
        for (int m = 0; m < 4; m++)
            p_sh[w * WIN + lane + 32 * m] = p[m] * inv;
        __syncwarp();

        float o0 = 0.0f, o1 = 0.0f;
        const float* vb = v_sh + j * KSTR;
        const float* pw = p_sh + w * WIN;
#pragma unroll 8
        for (int t = 0; t < WIN; t++) {
            float pp = pw[t];
            o0 += pp * vb[t * KSTR + lane];
            o1 += pp * vb[t * KSTR + lane + 32];
        }
        size_t ob = (size_t)(q0 + j) * HD + (size_t)h * HDIM;
        g_att[ob + lane]      = o0;
        g_att[ob + lane + 32] = o1;
        __syncwarp();
    }
}

// ============================ Launch ============================
extern "C" void kernel_launch(void* const* d_in, const int* in_sizes, int n_in,
                              void* d_out, int out_size) {
    (void)in_sizes; (void)n_in; (void)out_size;
    const float* x     = (const float*)d_in[0];
    const int*   pos   = (const int*)  d_in[1];
    const float* Wq    = (const float*)d_in[2];
    const float* bq    = (const float*)d_in[3];
    const float* Wk    = (const float*)d_in[4];
    const float* bk    = (const float*)d_in[5];
    const float* Wv    = (const float*)d_in[6];
    const float* bv    = (const float*)d_in[7];
    const float* Wo    = (const float*)d_in[8];
    const float* bo    = (const float*)d_in[9];
    const float* sinks = (const float*)d_in[10];
    float* out = (float*)d_out;

    size_t asz = (size_t)(2 * NKEY * KSTR + QT * 512 + 8 * WIN) * sizeof(float);
    cudaFuncSetAttribute(qkv_gemm,  cudaFuncAttributeMaxDynamicSharedMemorySize, GSMEM);
    cudaFuncSetAttribute(oproj_gemm, cudaFuncAttributeMaxDynamicSharedMemorySize, GSMEM);
    cudaFuncSetAttribute(attn_kernel, cudaFuncAttributeMaxDynamicSharedMemorySize, (int)asz);

    qkv_gemm<<<dim3(40, 8), 256, GSMEM>>>(x, Wq, bq, Wk, bk, Wv, bv);
    rope_kernel<<<SEQ, 256>>>(pos);
    attn_kernel<<<dim3(NKV, SEQ / QT), 256, asz>>>(sinks);
    oproj_gemm<<<dim3(23, 8), 256, GSMEM>>>(Wo, bo, out);
}